// round 4
// baseline (speedup 1.0000x reference)
#include <cuda_runtime.h>
#include <math.h>

// Problem constants
#define Bb 2
#define Tt 8
#define Mm 512
#define Dd 1024
#define Hh 1024
#define WIN 3
#define KNN 8
#define NROWS (Bb*Tt*Mm)      /* 8192 */
#define WM (WIN*Mm)           /* 1536 */
#define LN_EPS 1e-5f

// ---------------- scratch (device globals; no allocation allowed) -------------
__device__ float g_zn[NROWS*Dd];
__device__ float g_sim[(size_t)NROWS*WM];
__device__ float g_vals[NROWS*KNN];
__device__ int   g_idx[NROWS*KNN];
__device__ float g_agg[NROWS*Dd];
__device__ float g_X[NROWS*Dd];
__device__ float g_inp[NROWS*Dd];
__device__ float g_gi[(size_t)NROWS*3*Hh];
__device__ float g_gh[(size_t)Bb*Mm*3*Hh];
__device__ float g_mem[Bb*Mm*Hh];
__device__ float g_tmp[Bb*Mm*Dd];
__device__ float g_wksum[Dd];
__device__ float g_s0[Bb*Tt];

// valid (t, w) pairs:  t=0:{0}  t=1:{0,1}  t>=2:{0,1,2}  -> 21 pairs
__constant__ int c_pt[21] = {0,1,1,2,2,2,3,3,3,4,4,4,5,5,5,6,6,6,7,7,7};
__constant__ int c_pw[21] = {0,0,1,0,1,2,0,1,2,0,1,2,0,1,2,0,1,2,0,1,2};

// =============================== SGEMM (NT) ===================================
// C[i,j] = sum_d A[i,d] * W[j,d]   (+bias[j]) (+=C optional)
// 128x128 tile, BK=8, 256 threads, 8x8 per thread in 4 quadrants.
__global__ __launch_bounds__(256) void sgemm_nt(
    const float* __restrict__ A, const float* __restrict__ W,
    float* __restrict__ C, int N, int K,
    const float* __restrict__ bias, int accumulate)
{
    __shared__ __align__(16) float As[8][128];
    __shared__ __align__(16) float Bs[8][128];
    const int tid  = threadIdx.x;
    const int brow = blockIdx.y * 128;
    const int bcol = blockIdx.x * 128;
    const int tx = tid & 15, ty = tid >> 4;
    const int lrow = tid >> 1;
    const int lk   = (tid & 1) * 4;
    const float* Ap = A + (size_t)(brow + lrow) * K + lk;
    const float* Wp = W + (size_t)(bcol + lrow) * K + lk;

    float acc[2][2][4][4];
    #pragma unroll
    for (int a=0;a<2;a++)
      #pragma unroll
      for (int b=0;b<2;b++)
        #pragma unroll
        for (int i=0;i<4;i++)
          #pragma unroll
          for (int j=0;j<4;j++) acc[a][b][i][j] = 0.f;

    for (int k0 = 0; k0 < K; k0 += 8) {
        float4 a4 = *(const float4*)(Ap + k0);
        float4 b4 = *(const float4*)(Wp + k0);
        __syncthreads();
        As[lk+0][lrow]=a4.x; As[lk+1][lrow]=a4.y; As[lk+2][lrow]=a4.z; As[lk+3][lrow]=a4.w;
        Bs[lk+0][lrow]=b4.x; Bs[lk+1][lrow]=b4.y; Bs[lk+2][lrow]=b4.z; Bs[lk+3][lrow]=b4.w;
        __syncthreads();
        #pragma unroll
        for (int kk = 0; kk < 8; kk++) {
            float4 a0 = *(const float4*)&As[kk][ty*4];
            float4 a1 = *(const float4*)&As[kk][ty*4+64];
            float4 b0 = *(const float4*)&Bs[kk][tx*4];
            float4 b1 = *(const float4*)&Bs[kk][tx*4+64];
            float ra[2][4] = {{a0.x,a0.y,a0.z,a0.w},{a1.x,a1.y,a1.z,a1.w}};
            float rb[2][4] = {{b0.x,b0.y,b0.z,b0.w},{b1.x,b1.y,b1.z,b1.w}};
            #pragma unroll
            for (int ri=0;ri<2;ri++)
              #pragma unroll
              for (int ci=0;ci<2;ci++)
                #pragma unroll
                for (int i=0;i<4;i++)
                  #pragma unroll
                  for (int j=0;j<4;j++)
                    acc[ri][ci][i][j] += ra[ri][i]*rb[ci][j];
        }
    }
    #pragma unroll
    for (int ri=0;ri<2;ri++)
      #pragma unroll
      for (int i=0;i<4;i++) {
        int row = brow + ty*4 + ri*64 + i;
        #pragma unroll
        for (int ci=0;ci<2;ci++) {
          int col = bcol + tx*4 + ci*64;
          size_t o = (size_t)row*N + col;
          float4 v = make_float4(acc[ri][ci][i][0],acc[ri][ci][i][1],
                                 acc[ri][ci][i][2],acc[ri][ci][i][3]);
          if (bias) { float4 bb = *(const float4*)(bias + col);
                      v.x+=bb.x; v.y+=bb.y; v.z+=bb.z; v.w+=bb.w; }
          if (accumulate) { float4 c0 = *(const float4*)(C + o);
                            v.x+=c0.x; v.y+=c0.y; v.z+=c0.z; v.w+=c0.w; }
          *(float4*)(C + o) = v;
        }
      }
}

// sims: per (b, pair p=(t,w)):  C[m][n] = zn[b,t,m,:]·zn[b,t-w,n,:]
// written into g_sim row (b*T+t)*M+m at column slot w*M+n (ldc = WM)
__global__ __launch_bounds__(256) void sgemm_sim(void)
{
    const int pz = blockIdx.z;
    const int b = pz / 21, p = pz % 21;
    const int t = c_pt[p], w = c_pw[p];
    const float* A  = g_zn + (size_t)(b*Tt + t)     * Mm * Dd;
    const float* Wm = g_zn + (size_t)(b*Tt + (t-w)) * Mm * Dd;
    float* C = g_sim + (size_t)((b*Tt + t)*Mm) * WM + w*Mm;

    __shared__ __align__(16) float As[8][128];
    __shared__ __align__(16) float Bs[8][128];
    const int tid  = threadIdx.x;
    const int brow = blockIdx.y * 128;
    const int bcol = blockIdx.x * 128;
    const int tx = tid & 15, ty = tid >> 4;
    const int lrow = tid >> 1;
    const int lk   = (tid & 1) * 4;
    const float* Ap = A  + (size_t)(brow + lrow) * Dd + lk;
    const float* Wp = Wm + (size_t)(bcol + lrow) * Dd + lk;

    float acc[2][2][4][4];
    #pragma unroll
    for (int a=0;a<2;a++)
      #pragma unroll
      for (int bq=0;bq<2;bq++)
        #pragma unroll
        for (int i=0;i<4;i++)
          #pragma unroll
          for (int j=0;j<4;j++) acc[a][bq][i][j] = 0.f;

    for (int k0 = 0; k0 < Dd; k0 += 8) {
        float4 a4 = *(const float4*)(Ap + k0);
        float4 b4 = *(const float4*)(Wp + k0);
        __syncthreads();
        As[lk+0][lrow]=a4.x; As[lk+1][lrow]=a4.y; As[lk+2][lrow]=a4.z; As[lk+3][lrow]=a4.w;
        Bs[lk+0][lrow]=b4.x; Bs[lk+1][lrow]=b4.y; Bs[lk+2][lrow]=b4.z; Bs[lk+3][lrow]=b4.w;
        __syncthreads();
        #pragma unroll
        for (int kk = 0; kk < 8; kk++) {
            float4 a0 = *(const float4*)&As[kk][ty*4];
            float4 a1 = *(const float4*)&As[kk][ty*4+64];
            float4 b0 = *(const float4*)&Bs[kk][tx*4];
            float4 b1 = *(const float4*)&Bs[kk][tx*4+64];
            float ra[2][4] = {{a0.x,a0.y,a0.z,a0.w},{a1.x,a1.y,a1.z,a1.w}};
            float rb[2][4] = {{b0.x,b0.y,b0.z,b0.w},{b1.x,b1.y,b1.z,b1.w}};
            #pragma unroll
            for (int ri=0;ri<2;ri++)
              #pragma unroll
              for (int ci=0;ci<2;ci++)
                #pragma unroll
                for (int i=0;i<4;i++)
                  #pragma unroll
                  for (int j=0;j<4;j++)
                    acc[ri][ci][i][j] += ra[ri][i]*rb[ci][j];
        }
    }
    #pragma unroll
    for (int ri=0;ri<2;ri++)
      #pragma unroll
      for (int i=0;i<4;i++) {
        int row = brow + ty*4 + ri*64 + i;
        #pragma unroll
        for (int ci=0;ci<2;ci++) {
          int col = bcol + tx*4 + ci*64;
          *(float4*)(C + (size_t)row*WM + col) =
              make_float4(acc[ri][ci][i][0],acc[ri][ci][i][1],
                          acc[ri][ci][i][2],acc[ri][ci][i][3]);
        }
      }
}

// ============================ elementwise kernels =============================
__global__ void k_normalize(const float* __restrict__ z)
{
    const int row = blockIdx.x, tid = threadIdx.x;
    __shared__ float red[256];
    const float* src = z + (size_t)row*Dd;
    float s = 0.f;
    for (int d = tid; d < Dd; d += 256) { float v = src[d]; s += v*v; }
    red[tid] = s; __syncthreads();
    for (int st = 128; st > 0; st >>= 1) { if (tid < st) red[tid] += red[tid+st]; __syncthreads(); }
    const float inv = 1.0f / fmaxf(sqrtf(red[0]), 1e-12f);
    for (int d = tid; d < Dd; d += 256) g_zn[(size_t)row*Dd + d] = src[d]*inv;
}

__global__ void k_wksum(const float* __restrict__ Wk)
{
    int d = blockIdx.x*blockDim.x + threadIdx.x;
    if (d < Dd) {
        float s = 0.f;
        for (int r = 0; r < Dd; r++) s += Wk[(size_t)r*Dd + d];
        g_wksum[d] = s;
    }
}

__global__ void k_s0(const float* __restrict__ z, const float* __restrict__ Watt_q)
{
    const int bt = blockIdx.x, tid = threadIdx.x;
    __shared__ float red[256];
    const float* src = z + (size_t)(bt*Mm)*Dd;   // m = 0 row
    float s = 0.f;
    for (int d = tid; d < Dd; d += 256) s += src[d]*Watt_q[d];
    red[tid] = s; __syncthreads();
    for (int st = 128; st > 0; st >>= 1) { if (tid < st) red[tid] += red[tid+st]; __syncthreads(); }
    if (tid == 0) g_s0[bt] = red[0];
}

__global__ void k_fill_sim(void)
{
    size_t e = (size_t)blockIdx.x*256 + threadIdx.x;
    if (e < (size_t)NROWS*WM) g_sim[e] = -INFINITY;
}

__global__ void k_topk(void)
{
    const int row = blockIdx.x, tid = threadIdx.x;
    __shared__ float sv[WM];
    __shared__ float rv[256];
    __shared__ int   rix[256];
    for (int i = tid; i < WM; i += 256) sv[i] = g_sim[(size_t)row*WM + i];
    __syncthreads();
    for (int k = 0; k < KNN; k++) {
        float bv = -INFINITY; int bi = WM;
        for (int i = tid; i < WM; i += 256) {
            float v = sv[i];
            if (v > bv) { bv = v; bi = i; }
        }
        rv[tid] = bv; rix[tid] = bi; __syncthreads();
        for (int s = 128; s > 0; s >>= 1) {
            if (tid < s) {
                float v2 = rv[tid+s]; int i2 = rix[tid+s];
                if (v2 > rv[tid] || (v2 == rv[tid] && i2 < rix[tid])) { rv[tid]=v2; rix[tid]=i2; }
            }
            __syncthreads();
        }
        if (tid == 0) {
            g_vals[row*KNN+k] = rv[0];
            g_idx [row*KNN+k] = rix[0];
            sv[rix[0]] = -INFINITY;
        }
        __syncthreads();
    }
}

// gather Kfeat, kh = Kfeat·wksum, att = softmax(s0*kh), alpha = .5 vals + .5 att,
// agg = sum_k alpha_k * Kfeat_k
__global__ void k_attn_agg(const float* __restrict__ z)
{
    const int row = blockIdx.x, tid = threadIdx.x;   // 128 threads
    const int bt = row / Mm;
    const int t = bt % Tt, b = bt / Tt;
    __shared__ float kf[KNN][Dd];
    __shared__ float red[128];
    __shared__ float kh[KNN], alpha[KNN];
    for (int k = 0; k < KNN; k++) {
        int id = g_idx[row*KNN+k];
        int w = id / Mm, j = id - w*Mm;
        int tt = t - w; if (tt < 0) tt = 0;
        const float* src = z + (size_t)((b*Tt+tt)*Mm + j)*Dd;
        float part = 0.f;
        for (int d = tid; d < Dd; d += 128) { float v = src[d]; kf[k][d] = v; part += v*g_wksum[d]; }
        red[tid] = part; __syncthreads();
        for (int s = 64; s > 0; s >>= 1) { if (tid < s) red[tid] += red[tid+s]; __syncthreads(); }
        if (tid == 0) kh[k] = red[0];
        __syncthreads();
    }
    if (tid == 0) {
        float s = g_s0[bt];
        float l[KNN], mx = -INFINITY;
        for (int k = 0; k < KNN; k++) { l[k] = s*kh[k]; mx = fmaxf(mx, l[k]); }
        float sum = 0.f;
        for (int k = 0; k < KNN; k++) { l[k] = expf(l[k]-mx); sum += l[k]; }
        for (int k = 0; k < KNN; k++)
            alpha[k] = 0.5f*g_vals[row*KNN+k] + 0.5f*(l[k]/sum);
    }
    __syncthreads();
    for (int d = tid; d < Dd; d += 128) {
        float a = 0.f;
        #pragma unroll
        for (int k = 0; k < KNN; k++) a += alpha[k]*kf[k][d];
        g_agg[(size_t)row*Dd + d] = a;
    }
}

__global__ void k_layernorm(const float* __restrict__ lnw, const float* __restrict__ lnb)
{
    const int row = blockIdx.x, tid = threadIdx.x;
    __shared__ float xr[Dd];
    __shared__ float red[256];
    float* p = g_X + (size_t)row*Dd;
    float s = 0.f;
    for (int d = tid; d < Dd; d += 256) { float v = p[d]; xr[d] = v; s += v; }
    red[tid] = s; __syncthreads();
    for (int st = 128; st > 0; st >>= 1) { if (tid < st) red[tid] += red[tid+st]; __syncthreads(); }
    const float mu = red[0] * (1.0f/Dd);
    __syncthreads();
    float v2 = 0.f;
    for (int d = tid; d < Dd; d += 256) { float dv = xr[d]-mu; v2 += dv*dv; }
    red[tid] = v2; __syncthreads();
    for (int st = 128; st > 0; st >>= 1) { if (tid < st) red[tid] += red[tid+st]; __syncthreads(); }
    const float inv = 1.0f / sqrtf(red[0]*(1.0f/Dd) + LN_EPS);
    for (int d = tid; d < Dd; d += 256)
        p[d] = (xr[d]-mu)*inv*lnw[d] + lnb[d];
}

__global__ void k_zero_mem(void)
{
    int e = blockIdx.x*256 + threadIdx.x;
    if (e < Bb*Mm*Hh) g_mem[e] = 0.f;
}

__global__ void k_gru(int t)
{
    const int e = blockIdx.x*256 + threadIdx.x;       // 0 .. B*M*H-1
    const int i = e >> 10;                            // row: b*M+m
    const int hc = e & (Hh-1);
    const int b = i >> 9;
    const size_t gir = (size_t)(i + b*(Tt-1)*Mm + t*Mm);
    const float* gi = g_gi + gir*(3*Hh);
    const float* gh = g_gh + (size_t)i*(3*Hh);
    float r  = 1.f/(1.f + expf(-(gi[hc]        + gh[hc])));
    float zg = 1.f/(1.f + expf(-(gi[Hh+hc]     + gh[Hh+hc])));
    float n  = tanhf(gi[2*Hh+hc] + r*gh[2*Hh+hc]);
    size_t mo = (size_t)i*Hh + hc;
    float old = g_mem[mo];
    g_mem[mo] = (1.f - zg)*n + zg*old;
}

__global__ void k_out(const float* __restrict__ z, const float* __restrict__ bmf,
                      float* __restrict__ out_h, int t)
{
    const int e = blockIdx.x*256 + threadIdx.x;       // 0 .. B*M*D-1
    const int i = e >> 10;
    const int d = e & (Dd-1);
    const int b = i >> 9;
    const size_t zr = (size_t)(i + b*(Tt-1)*Mm + t*Mm);
    out_h[zr*Dd + d] = z[zr*Dd + d] + g_tmp[(size_t)i*Dd + d] + bmf[d];
}

__global__ void k_copy_mem(float* __restrict__ out_mem)
{
    int e = blockIdx.x*256 + threadIdx.x;
    if (e < Bb*Mm*Hh) out_mem[e] = g_mem[e];
}

// ================================ launch ======================================
extern "C" void kernel_launch(void* const* d_in, const int* in_sizes, int n_in,
                              void* d_out, int out_size)
{
    const float* z      = (const float*)d_in[0];
    const float* Wq     = (const float*)d_in[1];
    const float* Wv     = (const float*)d_in[2];
    const float* Wout   = (const float*)d_in[3];
    const float* ln_w   = (const float*)d_in[4];
    const float* ln_b   = (const float*)d_in[5];
    const float* Watt_q = (const float*)d_in[6];
    const float* Watt_k = (const float*)d_in[7];
    const float* W_ih   = (const float*)d_in[8];
    const float* W_hh   = (const float*)d_in[9];
    const float* b_ih   = (const float*)d_in[10];
    const float* b_hh   = (const float*)d_in[11];
    const float* W_mf   = (const float*)d_in[12];
    const float* b_mf   = (const float*)d_in[13];
    float* out     = (float*)d_out;
    float* out_h   = out;                            // (B,T,M,D)
    float* out_mem = out + (size_t)NROWS*Dd;         // (B,M,H)

    float *p_zn, *p_agg, *p_X, *p_inp, *p_gi, *p_gh, *p_mem, *p_tmp;
    cudaGetSymbolAddress((void**)&p_zn,  g_zn);
    cudaGetSymbolAddress((void**)&p_agg, g_agg);
    cudaGetSymbolAddress((void**)&p_X,   g_X);
    cudaGetSymbolAddress((void**)&p_inp, g_inp);
    cudaGetSymbolAddress((void**)&p_gi,  g_gi);
    cudaGetSymbolAddress((void**)&p_gh,  g_gh);
    cudaGetSymbolAddress((void**)&p_mem, g_mem);
    cudaGetSymbolAddress((void**)&p_tmp, g_tmp);

    // ---- parallel precompute over all t ----
    k_normalize<<<NROWS, 256>>>(z);
    k_wksum<<<Dd/256, 256>>>(Watt_k);
    k_s0<<<Bb*Tt, 256>>>(z, Watt_q);
    {
        size_t n = (size_t)NROWS*WM;
        k_fill_sim<<<(int)((n + 255)/256), 256>>>();
    }
    sgemm_sim<<<dim3(Mm/128, Mm/128, Bb*21), 256>>>();
    k_topk<<<NROWS, 256>>>();
    k_attn_agg<<<NROWS, 128>>>(z);

    // X = Z @ Wq^T ; X += agg @ Wv^T
    sgemm_nt<<<dim3(Dd/128, NROWS/128), 256>>>(z,     Wq, p_X, Dd, Dd, nullptr, 0);
    sgemm_nt<<<dim3(Dd/128, NROWS/128), 256>>>(p_agg, Wv, p_X, Dd, Dd, nullptr, 1);
    k_layernorm<<<NROWS, 256>>>(ln_w, ln_b);
    // inp = X @ Wout^T ; gi = inp @ W_ih^T + b_ih   (all t at once)
    sgemm_nt<<<dim3(Dd/128, NROWS/128), 256>>>(p_X,   Wout, p_inp, Dd, Dd, nullptr, 0);
    sgemm_nt<<<dim3(3*Hh/128, NROWS/128), 256>>>(p_inp, W_ih, p_gi, 3*Hh, Dd, b_ih, 0);

    // ---- sequential GRU ----
    k_zero_mem<<<(Bb*Mm*Hh)/256, 256>>>();
    for (int t = 0; t < Tt; t++) {
        sgemm_nt<<<dim3(3*Hh/128, (Bb*Mm)/128), 256>>>(p_mem, W_hh, p_gh, 3*Hh, Hh, b_hh, 0);
        k_gru<<<(Bb*Mm*Hh)/256, 256>>>(t);
        sgemm_nt<<<dim3(Dd/128, (Bb*Mm)/128), 256>>>(p_mem, W_mf, p_tmp, Dd, Hh, nullptr, 0);
        k_out<<<(Bb*Mm*Dd)/256, 256>>>(z, b_mf, out_h, t);
    }
    k_copy_mem<<<(Bb*Mm*Hh)/256, 256>>>(out_mem);
}

// round 6
// speedup vs baseline: 1.4533x; 1.4533x over previous
#include <cuda_runtime.h>
#include <math.h>

// Problem constants
#define Bb 2
#define Tt 8
#define Mm 512
#define Dd 1024
#define Hh 1024
#define WIN 3
#define KNN 8
#define NROWS (Bb*Tt*Mm)      /* 8192 */
#define WM (WIN*Mm)           /* 1536 */
#define LN_EPS 1e-5f

typedef unsigned long long ull;

// ---------------- scratch (device globals; no allocation allowed) -------------
__device__ float g_zn[NROWS*Dd];
__device__ float g_sim[(size_t)NROWS*WM];
__device__ float g_vals[NROWS*KNN];
__device__ int   g_idx[NROWS*KNN];
__device__ float g_agg[NROWS*Dd];
__device__ float g_X[NROWS*Dd];
__device__ float g_inp[NROWS*Dd];
__device__ float g_gi[(size_t)NROWS*3*Hh];
__device__ float g_gh[(size_t)Bb*Mm*3*Hh];
__device__ float g_mem[Bb*Mm*Hh];
__device__ float g_wksum[Dd];
__device__ float g_s0[Bb*Tt];

// valid (t, w) pairs:  t=0:{0}  t=1:{0,1}  t>=2:{0,1,2}  -> 21 pairs
__constant__ int c_pt[21] = {0,1,1,2,2,2,3,3,3,4,4,4,5,5,5,6,6,6,7,7,7};
__constant__ int c_pw[21] = {0,0,1,0,1,2,0,1,2,0,1,2,0,1,2,0,1,2,0,1,2};

// ============================ FFMA2 GEMM core =================================
// 128x128 tile, BK=16, double-buffered smem, 256 threads, 8x8 per thread.
// Inner product uses packed fma.rn.f32x2 (FFMA2) -> 2x fp32 throughput.
// acc2[i][jp]: i = 8 output rows (ty*4+{0..3}, ty*4+64+{0..3}),
//              jp = 4 col-pairs (tx*4+{0,1},{2,3}, tx*4+64+{0,1},{2,3})

__device__ __forceinline__ void ffma2(ull& d, ull a, ull b) {
    asm("fma.rn.f32x2 %0, %1, %2, %0;" : "+l"(d) : "l"(a), "l"(b));
}
__device__ __forceinline__ ull pack_dup(float x) {
    ull r; unsigned u = __float_as_uint(x);
    asm("mov.b64 %0, {%1, %1};" : "=l"(r) : "r"(u));
    return r;
}

#define GEMM_STORE_TILE(bufi)                                                  \
    As[bufi][lk8+0][lrow]=ra0.x; As[bufi][lk8+1][lrow]=ra0.y;                  \
    As[bufi][lk8+2][lrow]=ra0.z; As[bufi][lk8+3][lrow]=ra0.w;                  \
    As[bufi][lk8+4][lrow]=ra1.x; As[bufi][lk8+5][lrow]=ra1.y;                  \
    As[bufi][lk8+6][lrow]=ra1.z; As[bufi][lk8+7][lrow]=ra1.w;                  \
    Bs[bufi][lk8+0][lrow]=rb0.x; Bs[bufi][lk8+1][lrow]=rb0.y;                  \
    Bs[bufi][lk8+2][lrow]=rb0.z; Bs[bufi][lk8+3][lrow]=rb0.w;                  \
    Bs[bufi][lk8+4][lrow]=rb1.x; Bs[bufi][lk8+5][lrow]=rb1.y;                  \
    Bs[bufi][lk8+6][lrow]=rb1.z; Bs[bufi][lk8+7][lrow]=rb1.w;

__device__ __forceinline__ void gemm_mainloop(
    const float* __restrict__ Ap, const float* __restrict__ Wp, int K,
    float (&As)[2][16][128], float (&Bs)[2][16][128],
    ull (&acc2)[8][4], int tid)
{
    const int tx = tid & 15, ty = tid >> 4;
    const int lrow = tid >> 1;
    const int lk8  = (tid & 1) * 8;
    (void)lk8;

    float4 ra0 = *(const float4*)(Ap);
    float4 ra1 = *(const float4*)(Ap + 4);
    float4 rb0 = *(const float4*)(Wp);
    float4 rb1 = *(const float4*)(Wp + 4);
    GEMM_STORE_TILE(0)
    __syncthreads();

    int buf = 0;
    for (int k0 = 16; k0 <= K; k0 += 16) {
        const bool more = (k0 < K);
        if (more) {
            ra0 = *(const float4*)(Ap + k0);
            ra1 = *(const float4*)(Ap + k0 + 4);
            rb0 = *(const float4*)(Wp + k0);
            rb1 = *(const float4*)(Wp + k0 + 4);
        }
        #pragma unroll
        for (int kk = 0; kk < 16; kk++) {
            float4 a0 = *(const float4*)&As[buf][kk][ty*4];
            float4 a1 = *(const float4*)&As[buf][kk][ty*4+64];
            ulonglong2 b0 = *(const ulonglong2*)&Bs[buf][kk][tx*4];
            ulonglong2 b1 = *(const ulonglong2*)&Bs[buf][kk][tx*4+64];
            ull pb[4] = {b0.x, b0.y, b1.x, b1.y};
            float fa[8] = {a0.x,a0.y,a0.z,a0.w,a1.x,a1.y,a1.z,a1.w};
            #pragma unroll
            for (int i = 0; i < 8; i++) {
                ull pa = pack_dup(fa[i]);
                #pragma unroll
                for (int jp = 0; jp < 4; jp++) ffma2(acc2[i][jp], pa, pb[jp]);
            }
        }
        if (more) {
            const int nb = buf ^ 1;
            GEMM_STORE_TILE(nb)
        }
        __syncthreads();
        buf ^= 1;
    }
}

__device__ __forceinline__ void acc_row(ull (&acc2)[8][4], int i,
                                        float4& v0, float4& v1)
{
    float2 p0 = *(float2*)&acc2[i][0];
    float2 p1 = *(float2*)&acc2[i][1];
    float2 p2 = *(float2*)&acc2[i][2];
    float2 p3 = *(float2*)&acc2[i][3];
    v0 = make_float4(p0.x, p0.y, p1.x, p1.y);
    v1 = make_float4(p2.x, p2.y, p3.x, p3.y);
}

// ---- generic NT GEMM: C[i,j] = sum_d A[i,d]*W[j,d] (+bias[j]) (+=C) ----------
__global__ __launch_bounds__(256,2) void sgemm_nt(
    const float* __restrict__ A, const float* __restrict__ W,
    float* __restrict__ C, int N, int K,
    const float* __restrict__ bias, int accumulate)
{
    __shared__ float As[2][16][128];
    __shared__ float Bs[2][16][128];
    const int tid  = threadIdx.x;
    const int brow = blockIdx.y * 128;
    const int bcol = blockIdx.x * 128;
    const int tx = tid & 15, ty = tid >> 4;
    const int lrow = tid >> 1;
    const int lk8  = (tid & 1) * 8;
    const float* Ap = A + (size_t)(brow + lrow) * K + lk8;
    const float* Wp = W + (size_t)(bcol + lrow) * K + lk8;

    ull acc2[8][4];
    #pragma unroll
    for (int i=0;i<8;i++)
      #pragma unroll
      for (int j=0;j<4;j++) acc2[i][j] = 0ull;

    gemm_mainloop(Ap, Wp, K, As, Bs, acc2, tid);

    #pragma unroll
    for (int i = 0; i < 8; i++) {
        const int row = brow + ty*4 + (i < 4 ? i : i + 60);
        float4 v0, v1; acc_row(acc2, i, v0, v1);
        const int c0 = bcol + tx*4, c1 = c0 + 64;
        if (bias) {
            float4 b0 = *(const float4*)(bias + c0);
            float4 b1 = *(const float4*)(bias + c1);
            v0.x+=b0.x; v0.y+=b0.y; v0.z+=b0.z; v0.w+=b0.w;
            v1.x+=b1.x; v1.y+=b1.y; v1.z+=b1.z; v1.w+=b1.w;
        }
        size_t o0 = (size_t)row*N + c0, o1 = (size_t)row*N + c1;
        if (accumulate) {
            float4 d0 = *(const float4*)(C + o0);
            float4 d1 = *(const float4*)(C + o1);
            v0.x+=d0.x; v0.y+=d0.y; v0.z+=d0.z; v0.w+=d0.w;
            v1.x+=d1.x; v1.y+=d1.y; v1.z+=d1.z; v1.w+=d1.w;
        }
        *(float4*)(C + o0) = v0;
        *(float4*)(C + o1) = v1;
    }
}

// ---- sim Gram blocks: C[m][n] = zn[b,t,m,:]·zn[b,t-w,n,:] --------------------
__global__ __launch_bounds__(256,2) void sgemm_sim(void)
{
    const int pz = blockIdx.z;
    const int b = pz / 21, p = pz % 21;
    const int t = c_pt[p], w = c_pw[p];
    const float* A  = g_zn + (size_t)(b*Tt + t)     * Mm * Dd;
    const float* Wm = g_zn + (size_t)(b*Tt + (t-w)) * Mm * Dd;
    float* C = g_sim + (size_t)((b*Tt + t)*Mm) * WM + w*Mm;

    __shared__ float As[2][16][128];
    __shared__ float Bs[2][16][128];
    const int tid  = threadIdx.x;
    const int brow = blockIdx.y * 128;
    const int bcol = blockIdx.x * 128;
    const int tx = tid & 15, ty = tid >> 4;
    const int lrow = tid >> 1;
    const int lk8  = (tid & 1) * 8;
    const float* Ap = A  + (size_t)(brow + lrow) * Dd + lk8;
    const float* Wp = Wm + (size_t)(bcol + lrow) * Dd + lk8;

    ull acc2[8][4];
    #pragma unroll
    for (int i=0;i<8;i++)
      #pragma unroll
      for (int j=0;j<4;j++) acc2[i][j] = 0ull;

    gemm_mainloop(Ap, Wp, Dd, As, Bs, acc2, tid);

    #pragma unroll
    for (int i = 0; i < 8; i++) {
        const int row = brow + ty*4 + (i < 4 ? i : i + 60);
        float4 v0, v1; acc_row(acc2, i, v0, v1);
        *(float4*)(C + (size_t)row*WM + bcol + tx*4)      = v0;
        *(float4*)(C + (size_t)row*WM + bcol + tx*4 + 64) = v1;
    }
}

// ---- fused sequential GEMM: [gh | out] = mem @ [W_hh | W_mf]^T + epilogue ----
// N = 4*Hh = 4096 total columns; cols [0,3072) -> g_gh (+b_hh),
// cols [3072,4096) -> out_h[t] = acc + z[:,t] + b_mf
__global__ __launch_bounds__(256,2) void sgemm_seq(
    const float* __restrict__ Whh, const float* __restrict__ Wmf,
    const float* __restrict__ bhh, const float* __restrict__ bmf,
    const float* __restrict__ z, float* __restrict__ out_h, int t)
{
    __shared__ float As[2][16][128];
    __shared__ float Bs[2][16][128];
    const int tid  = threadIdx.x;
    const int brow = blockIdx.y * 128;
    const int bcol = blockIdx.x * 128;
    const bool is_mf = (bcol >= 3*Hh);
    const float* W = is_mf ? (Wmf + (size_t)(bcol - 3*Hh) * Hh)
                           : (Whh + (size_t)bcol * Hh);
    const int tx = tid & 15, ty = tid >> 4;
    const int lrow = tid >> 1;
    const int lk8  = (tid & 1) * 8;
    const float* Ap = g_mem + (size_t)(brow + lrow) * Hh + lk8;
    const float* Wp = W + (size_t)lrow * Hh + lk8;

    ull acc2[8][4];
    #pragma unroll
    for (int i=0;i<8;i++)
      #pragma unroll
      for (int j=0;j<4;j++) acc2[i][j] = 0ull;

    gemm_mainloop(Ap, Wp, Hh, As, Bs, acc2, tid);

    #pragma unroll
    for (int i = 0; i < 8; i++) {
        const int r = brow + ty*4 + (i < 4 ? i : i + 60);   // 0..1023
        float4 v0, v1; acc_row(acc2, i, v0, v1);
        if (!is_mf) {
            const int c0 = bcol + tx*4, c1 = c0 + 64;
            float4 b0 = *(const float4*)(bhh + c0);
            float4 b1 = *(const float4*)(bhh + c1);
            v0.x+=b0.x; v0.y+=b0.y; v0.z+=b0.z; v0.w+=b0.w;
            v1.x+=b1.x; v1.y+=b1.y; v1.z+=b1.z; v1.w+=b1.w;
            *(float4*)(g_gh + (size_t)r*(3*Hh) + c0) = v0;
            *(float4*)(g_gh + (size_t)r*(3*Hh) + c1) = v1;
        } else {
            const int j0 = bcol - 3*Hh + tx*4, j1 = j0 + 64;
            const int b = r >> 9, m = r & 511;
            const size_t zr = (size_t)((b*Tt + t)*Mm + m) * Dd;
            float4 z0 = *(const float4*)(z + zr + j0);
            float4 z1 = *(const float4*)(z + zr + j1);
            float4 b0 = *(const float4*)(bmf + j0);
            float4 b1 = *(const float4*)(bmf + j1);
            v0.x+=z0.x+b0.x; v0.y+=z0.y+b0.y; v0.z+=z0.z+b0.z; v0.w+=z0.w+b0.w;
            v1.x+=z1.x+b1.x; v1.y+=z1.y+b1.y; v1.z+=z1.z+b1.z; v1.w+=z1.w+b1.w;
            *(float4*)(out_h + zr + j0) = v0;
            *(float4*)(out_h + zr + j1) = v1;
        }
    }
}

// ============================ elementwise kernels =============================
__global__ void k_normalize(const float* __restrict__ z)
{
    const int row = blockIdx.x, tid = threadIdx.x;
    __shared__ float red[256];
    const float* src = z + (size_t)row*Dd;
    float s = 0.f;
    for (int d = tid; d < Dd; d += 256) { float v = src[d]; s += v*v; }
    red[tid] = s; __syncthreads();
    for (int st = 128; st > 0; st >>= 1) { if (tid < st) red[tid] += red[tid+st]; __syncthreads(); }
    const float inv = 1.0f / fmaxf(sqrtf(red[0]), 1e-12f);
    for (int d = tid; d < Dd; d += 256) g_zn[(size_t)row*Dd + d] = src[d]*inv;
}

__global__ void k_wksum(const float* __restrict__ Wk)
{
    int d = blockIdx.x*blockDim.x + threadIdx.x;
    if (d < Dd) {
        float s = 0.f;
        for (int r = 0; r < Dd; r++) s += Wk[(size_t)r*Dd + d];
        g_wksum[d] = s;
    }
}

__global__ void k_s0(const float* __restrict__ z, const float* __restrict__ Watt_q)
{
    const int bt = blockIdx.x, tid = threadIdx.x;
    __shared__ float red[256];
    const float* src = z + (size_t)(bt*Mm)*Dd;   // m = 0 row
    float s = 0.f;
    for (int d = tid; d < Dd; d += 256) s += src[d]*Watt_q[d];
    red[tid] = s; __syncthreads();
    for (int st = 128; st > 0; st >>= 1) { if (tid < st) red[tid] += red[tid+st]; __syncthreads(); }
    if (tid == 0) g_s0[bt] = red[0];
}

__global__ void k_topk(void)
{
    const int row = blockIdx.x, tid = threadIdx.x;
    const int t = (row / Mm) % Tt;
    const int limit = (t >= 2 ? 3 : t + 1) * Mm;
    __shared__ float sv[WM];
    __shared__ float rv[256];
    __shared__ int   rix[256];
    for (int i = tid; i < limit; i += 256) sv[i] = g_sim[(size_t)row*WM + i];
    __syncthreads();
    for (int k = 0; k < KNN; k++) {
        float bv = -INFINITY; int bi = WM;
        for (int i = tid; i < limit; i += 256) {
            float v = sv[i];
            if (v > bv) { bv = v; bi = i; }
        }
        rv[tid] = bv; rix[tid] = bi; __syncthreads();
        for (int s = 128; s > 0; s >>= 1) {
            if (tid < s) {
                float v2 = rv[tid+s]; int i2 = rix[tid+s];
                if (v2 > rv[tid] || (v2 == rv[tid] && i2 < rix[tid])) { rv[tid]=v2; rix[tid]=i2; }
            }
            __syncthreads();
        }
        if (tid == 0) {
            g_vals[row*KNN+k] = rv[0];
            g_idx [row*KNN+k] = rix[0];
            sv[rix[0]] = -INFINITY;
        }
        __syncthreads();
    }
}

// gather Kfeat, kh = Kfeat·wksum, att = softmax(s0*kh), alpha = .5 vals + .5 att,
// agg = sum_k alpha_k * Kfeat_k
__global__ void k_attn_agg(const float* __restrict__ z)
{
    const int row = blockIdx.x, tid = threadIdx.x;   // 128 threads
    const int bt = row / Mm;
    const int t = bt % Tt, b = bt / Tt;
    __shared__ float kf[KNN][Dd];
    __shared__ float red[128];
    __shared__ float kh[KNN], alpha[KNN];
    for (int k = 0; k < KNN; k++) {
        int id = g_idx[row*KNN+k];
        int w = id / Mm, j = id - w*Mm;
        int tt = t - w; if (tt < 0) tt = 0;
        const float* src = z + (size_t)((b*Tt+tt)*Mm + j)*Dd;
        float part = 0.f;
        for (int d = tid; d < Dd; d += 128) { float v = src[d]; kf[k][d] = v; part += v*g_wksum[d]; }
        red[tid] = part; __syncthreads();
        for (int s = 64; s > 0; s >>= 1) { if (tid < s) red[tid] += red[tid+s]; __syncthreads(); }
        if (tid == 0) kh[k] = red[0];
        __syncthreads();
    }
    if (tid == 0) {
        float s = g_s0[bt];
        float l[KNN], mx = -INFINITY;
        for (int k = 0; k < KNN; k++) { l[k] = s*kh[k]; mx = fmaxf(mx, l[k]); }
        float sum = 0.f;
        for (int k = 0; k < KNN; k++) { l[k] = expf(l[k]-mx); sum += l[k]; }
        for (int k = 0; k < KNN; k++)
            alpha[k] = 0.5f*g_vals[row*KNN+k] + 0.5f*(l[k]/sum);
    }
    __syncthreads();
    for (int d = tid; d < Dd; d += 128) {
        float a = 0.f;
        #pragma unroll
        for (int k = 0; k < KNN; k++) a += alpha[k]*kf[k][d];
        g_agg[(size_t)row*Dd + d] = a;
    }
}

__global__ void k_layernorm(const float* __restrict__ lnw, const float* __restrict__ lnb)
{
    const int row = blockIdx.x, tid = threadIdx.x;
    __shared__ float xr[Dd];
    __shared__ float red[256];
    float* p = g_X + (size_t)row*Dd;
    float s = 0.f;
    for (int d = tid; d < Dd; d += 256) { float v = p[d]; xr[d] = v; s += v; }
    red[tid] = s; __syncthreads();
    for (int st = 128; st > 0; st >>= 1) { if (tid < st) red[tid] += red[tid+st]; __syncthreads(); }
    const float mu = red[0] * (1.0f/Dd);
    __syncthreads();
    float v2 = 0.f;
    for (int d = tid; d < Dd; d += 256) { float dv = xr[d]-mu; v2 += dv*dv; }
    red[tid] = v2; __syncthreads();
    for (int st = 128; st > 0; st >>= 1) { if (tid < st) red[tid] += red[tid+st]; __syncthreads(); }
    const float inv = 1.0f / sqrtf(red[0]*(1.0f/Dd) + LN_EPS);
    for (int d = tid; d < Dd; d += 256)
        p[d] = (xr[d]-mu)*inv*lnw[d] + lnb[d];
}

__global__ void k_zero_mem(void)
{
    int e = blockIdx.x*256 + threadIdx.x;
    if (e < Bb*Mm*Hh) g_mem[e] = 0.f;
}

__global__ void k_init_gh(const float* __restrict__ bhh)
{
    int e = blockIdx.x*256 + threadIdx.x;          // < Bb*Mm*3*Hh
    g_gh[e] = bhh[e % (3*Hh)];
}

__global__ void k_gru(int t)
{
    const int e = blockIdx.x*256 + threadIdx.x;       // 0 .. B*M*H-1
    const int i = e >> 10;                            // row: b*M+m
    const int hc = e & (Hh-1);
    const int b = i >> 9;
    const size_t gir = (size_t)(i + b*(Tt-1)*Mm + t*Mm);
    const float* gi = g_gi + gir*(3*Hh);
    const float* gh = g_gh + (size_t)i*(3*Hh);
    float r  = 1.f/(1.f + expf(-(gi[hc]        + gh[hc])));
    float zg = 1.f/(1.f + expf(-(gi[Hh+hc]     + gh[Hh+hc])));
    float n  = tanhf(gi[2*Hh+hc] + r*gh[2*Hh+hc]);
    size_t mo = (size_t)i*Hh + hc;
    float old = g_mem[mo];
    g_mem[mo] = (1.f - zg)*n + zg*old;
}

__global__ void k_copy_mem(float* __restrict__ out_mem)
{
    int e = blockIdx.x*256 + threadIdx.x;
    if (e < Bb*Mm*Hh) out_mem[e] = g_mem[e];
}

// ================================ launch ======================================
extern "C" void kernel_launch(void* const* d_in, const int* in_sizes, int n_in,
                              void* d_out, int out_size)
{
    const float* z      = (const float*)d_in[0];
    const float* Wq     = (const float*)d_in[1];
    const float* Wv     = (const float*)d_in[2];
    const float* Wout   = (const float*)d_in[3];
    const float* ln_w   = (const float*)d_in[4];
    const float* ln_b   = (const float*)d_in[5];
    const float* Watt_q = (const float*)d_in[6];
    const float* Watt_k = (const float*)d_in[7];
    const float* W_ih   = (const float*)d_in[8];
    const float* W_hh   = (const float*)d_in[9];
    const float* b_ih   = (const float*)d_in[10];
    const float* b_hh   = (const float*)d_in[11];
    const float* W_mf   = (const float*)d_in[12];
    const float* b_mf   = (const float*)d_in[13];
    float* out     = (float*)d_out;
    float* out_h   = out;                            // (B,T,M,D)
    float* out_mem = out + (size_t)NROWS*Dd;         // (B,M,H)

    float *p_agg, *p_X, *p_inp, *p_gi;
    cudaGetSymbolAddress((void**)&p_agg, g_agg);
    cudaGetSymbolAddress((void**)&p_X,   g_X);
    cudaGetSymbolAddress((void**)&p_inp, g_inp);
    cudaGetSymbolAddress((void**)&p_gi,  g_gi);

    // ---- parallel precompute over all t ----
    k_normalize<<<NROWS, 256>>>(z);
    k_wksum<<<Dd/256, 256>>>(Watt_k);
    k_s0<<<Bb*Tt, 256>>>(z, Watt_q);
    sgemm_sim<<<dim3(Mm/128, Mm/128, Bb*21), 256>>>();
    k_topk<<<NROWS, 256>>>();
    k_attn_agg<<<NROWS, 128>>>(z);

    // X = Z @ Wq^T ; X += agg @ Wv^T
    sgemm_nt<<<dim3(Dd/128, NROWS/128), 256>>>(z,     Wq, p_X, Dd, Dd, nullptr, 0);
    sgemm_nt<<<dim3(Dd/128, NROWS/128), 256>>>(p_agg, Wv, p_X, Dd, Dd, nullptr, 1);
    k_layernorm<<<NROWS, 256>>>(ln_w, ln_b);
    // inp = X @ Wout^T ; gi = inp @ W_ih^T + b_ih   (all t at once)
    sgemm_nt<<<dim3(Dd/128, NROWS/128), 256>>>(p_X,   Wout, p_inp, Dd, Dd, nullptr, 0);
    sgemm_nt<<<dim3(3*Hh/128, NROWS/128), 256>>>(p_inp, W_ih, p_gi, 3*Hh, Dd, b_ih, 0);

    // ---- sequential GRU ----
    k_zero_mem<<<(Bb*Mm*Hh)/256, 256>>>();
    k_init_gh<<<(Bb*Mm*3*Hh)/256, 256>>>(b_hh);        // gh for t=0 (mem=0)
    for (int t = 0; t < Tt; t++) {
        k_gru<<<(Bb*Mm*Hh)/256, 256>>>(t);             // mem <- mem_{t+1}
        // [gh | out_h(t)] = mem @ [W_hh | W_mf]^T  (+b_hh / +z+b_mf)
        sgemm_seq<<<dim3(4*Hh/128, (Bb*Mm)/128), 256>>>(
            W_hh, W_mf, b_hh, b_mf, z, out_h, t);
    }
    k_copy_mem<<<(Bb*Mm*Hh)/256, 256>>>(out_mem);
}

// round 8
// speedup vs baseline: 2.2613x; 1.5560x over previous
#include <cuda_runtime.h>
#include <cuda_bf16.h>
#include <math.h>
#include <stdint.h>

// Problem constants
#define Bb 2
#define Tt 8
#define Mm 512
#define Dd 1024
#define Hh 1024
#define WIN 3
#define KNN 8
#define NROWS (Bb*Tt*Mm)      /* 8192 */
#define WM (WIN*Mm)           /* 1536 */
#define LN_EPS 1e-5f
#define KT 3072               /* tripled K: [hi|lo|hi] x [hi|hi|lo] */

// ---------------- scratch (device globals; no allocation allowed) -------------
__device__ float g_sim[(size_t)NROWS*WM];
__device__ float g_vals[NROWS*KNN];
__device__ int   g_idx[NROWS*KNN];
__device__ float g_X[NROWS*Dd];
__device__ float g_gi[(size_t)NROWS*3*Hh];
__device__ float g_gh[(size_t)Bb*Mm*3*Hh];
__device__ float g_mem[Bb*Mm*Hh];
__device__ float g_wksum[Dd];
__device__ float g_s0[Bb*Tt];

// bf16 tripled-K operand copies (16B aligned for uint4 loads)
__device__ __align__(16) __nv_bfloat16 g_znA[(size_t)NROWS*KT];
__device__ __align__(16) __nv_bfloat16 g_znB[(size_t)NROWS*KT];
__device__ __align__(16) __nv_bfloat16 g_zA [(size_t)NROWS*KT];
__device__ __align__(16) __nv_bfloat16 g_aggA[(size_t)NROWS*KT];
__device__ __align__(16) __nv_bfloat16 g_XlnA[(size_t)NROWS*KT];
__device__ __align__(16) __nv_bfloat16 g_inpA[(size_t)NROWS*KT];
__device__ __align__(16) __nv_bfloat16 g_memA[(size_t)Bb*Mm*KT];
__device__ __align__(16) __nv_bfloat16 g_WqB [(size_t)Dd*KT];
__device__ __align__(16) __nv_bfloat16 g_WvB [(size_t)Dd*KT];
__device__ __align__(16) __nv_bfloat16 g_WoutB[(size_t)Dd*KT];
__device__ __align__(16) __nv_bfloat16 g_WihB[(size_t)3*Hh*KT];
__device__ __align__(16) __nv_bfloat16 g_WhhB[(size_t)3*Hh*KT];
__device__ __align__(16) __nv_bfloat16 g_WmfB[(size_t)Dd*KT];

// valid (t, w) pairs
__constant__ int c_pt[21] = {0,1,1,2,2,2,3,3,3,4,4,4,5,5,5,6,6,6,7,7,7};
__constant__ int c_pw[21] = {0,0,1,0,1,2,0,1,2,0,1,2,0,1,2,0,1,2,0,1,2};

// ============================ helpers =========================================
__device__ __forceinline__ uint32_t smem_u32(const void* p){
    uint32_t a;
    asm("{ .reg .u64 t; cvta.to.shared.u64 t, %1; cvt.u32.u64 %0, t; }"
        : "=r"(a) : "l"(p));
    return a;
}
__device__ __forceinline__ void split2(float x, __nv_bfloat16& h, __nv_bfloat16& l){
    h = __float2bfloat16(x);
    l = __float2bfloat16(x - __bfloat162float(h));
}
#define LDSM4(r, a)                                                             \
    asm volatile("ldmatrix.sync.aligned.m8n8.x4.shared.b16 {%0,%1,%2,%3}, [%4];"\
        : "=r"((r)[0]), "=r"((r)[1]), "=r"((r)[2]), "=r"((r)[3]) : "r"(a))
#define MMA16816(c, a, b0v, b1v)                                                \
    asm volatile("mma.sync.aligned.m16n8k16.row.col.f32.bf16.bf16.f32 "         \
        "{%0,%1,%2,%3}, {%4,%5,%6,%7}, {%8,%9}, {%0,%1,%2,%3};"                 \
        : "+f"((c)[0]), "+f"((c)[1]), "+f"((c)[2]), "+f"((c)[3])                \
        : "r"((a)[0]), "r"((a)[1]), "r"((a)[2]), "r"((a)[3]),                   \
          "r"(b0v), "r"(b1v))

// ============================ mma.sync GEMM ===================================
// C[i,j] = sum A[i,:]*W[j,:], bf16 tripled-K (KT=3072 per segment).
// BM=128, BN=128, BK=32. 8 warps (2m x 4n), warp tile 64x32.
// smem: padded stride 80B per 32-elem bf16 row (conflict-free ldmatrix).
#define BM 128
#define BN 128
#define BK 32
#define SSTR 80
#define STG  (128*SSTR)        /* 10240 B per operand stage */

// tasks: 0=sim  1=X(z@Wq + agg@Wv)  2=inp(Xln@Wout, split-out)  3=gi(+b1)
//        4=seq(mem@[Whh|Wmf]; gh=+b1 / out=+z+b2)
__global__ __launch_bounds__(256,2) void gemm_mma(
    int task, int t, const float* __restrict__ b1, const float* __restrict__ b2,
    const float* __restrict__ zin, float* __restrict__ outp)
{
    __shared__ __align__(16) char smem[4*STG];
    const int tid  = threadIdx.x;
    const int wid  = tid >> 5, lane = tid & 31;
    const int brow = blockIdx.y * BM;
    const int bcol = blockIdx.x * BN;
    const int warp_m = (wid & 1) * 64;
    const int warp_n = (wid >> 1) * 32;

    const __nv_bfloat16 *A0=0, *A1=0, *W0=0, *W1=0;
    int nseg = 1, b = 0, w = 0, tt = 0;
    if (task == 0) {
        int bz = blockIdx.z; b = bz/21; int p = bz%21; tt = c_pt[p]; w = c_pw[p];
        A0 = g_znA + (size_t)((b*Tt+tt)*Mm + brow)*KT;
        W0 = g_znB + (size_t)((b*Tt+(tt-w))*Mm + bcol)*KT;
    } else if (task == 1) {
        A0 = g_zA   + (size_t)brow*KT; W0 = g_WqB + (size_t)bcol*KT;
        A1 = g_aggA + (size_t)brow*KT; W1 = g_WvB + (size_t)bcol*KT; nseg = 2;
    } else if (task == 2) {
        A0 = g_XlnA + (size_t)brow*KT; W0 = g_WoutB + (size_t)bcol*KT;
    } else if (task == 3) {
        A0 = g_inpA + (size_t)brow*KT; W0 = g_WihB + (size_t)bcol*KT;
    } else {
        A0 = g_memA + (size_t)brow*KT;
        W0 = (bcol < 3*Hh) ? (g_WhhB + (size_t)bcol*KT)
                           : (g_WmfB + (size_t)(bcol - 3*Hh)*KT);
    }

    const uint32_t sbase = smem_u32(smem);
    const uint32_t sA[2] = {sbase,         sbase + 2*STG};
    const uint32_t sB[2] = {sbase + STG,   sbase + 3*STG};

    // ldg mapping: 512 16B-chunks per operand stage; thread -> rows r, r+64, col (tid&3)*8
    const int lr  = tid >> 2;            // 0..63
    const int lc  = (tid & 3) * 8;       // element col within BK
    const uint32_t sts_off = (uint32_t)lr*SSTR + (uint32_t)(tid & 3)*16;

    // ldmatrix per-lane addressing
    const uint32_t aRow  = (uint32_t)(warp_m + (lane & 15));
    const uint32_t bRow  = (uint32_t)(warp_n + (lane & 15));
    const uint32_t chnk  = (uint32_t)((lane >> 4) * 16);

    float acc[4][4][4];
    #pragma unroll
    for (int i=0;i<4;i++)
      #pragma unroll
      for (int j=0;j<4;j++)
        #pragma unroll
        for (int k=0;k<4;k++) acc[i][j][k] = 0.f;

    const int S = nseg * (KT/BK);
    uint4 ra0, ra1, rb0, rb1;

    // prologue: stage 0
    {
        ra0 = *(const uint4*)(A0 + (size_t)lr*KT + lc);
        ra1 = *(const uint4*)(A0 + (size_t)(lr+64)*KT + lc);
        rb0 = *(const uint4*)(W0 + (size_t)lr*KT + lc);
        rb1 = *(const uint4*)(W0 + (size_t)(lr+64)*KT + lc);
        *(uint4*)(smem + (sts_off))              = ra0;
        *(uint4*)(smem + (sts_off + 64*SSTR))    = ra1;
        *(uint4*)(smem + (STG + sts_off))        = rb0;
        *(uint4*)(smem + (STG + sts_off + 64*SSTR)) = rb1;
    }
    __syncthreads();

    for (int s = 0; s < S; s++) {
        const int buf = s & 1;
        if (s + 1 < S) {
            const int sn  = s + 1;
            const int seg = sn >= (KT/BK);
            const int k0  = (sn - seg*(KT/BK)) * BK;
            const __nv_bfloat16* Ab = (seg ? A1 : A0);
            const __nv_bfloat16* Wb = (seg ? W1 : W0);
            ra0 = *(const uint4*)(Ab + (size_t)lr*KT + k0 + lc);
            ra1 = *(const uint4*)(Ab + (size_t)(lr+64)*KT + k0 + lc);
            rb0 = *(const uint4*)(Wb + (size_t)lr*KT + k0 + lc);
            rb1 = *(const uint4*)(Wb + (size_t)(lr+64)*KT + k0 + lc);
        }
        // compute stage s from buf
        #pragma unroll
        for (int kk = 0; kk < 2; kk++) {
            uint32_t afr[4][4], bfr[2][4];
            #pragma unroll
            for (int mt = 0; mt < 4; mt++)
                LDSM4(afr[mt], sA[buf] + (aRow + mt*16)*SSTR + kk*32 + chnk);
            #pragma unroll
            for (int nt = 0; nt < 2; nt++)
                LDSM4(bfr[nt], sB[buf] + (bRow + nt*16)*SSTR + kk*32 + chnk);
            #pragma unroll
            for (int mt = 0; mt < 4; mt++)
                #pragma unroll
                for (int n8 = 0; n8 < 4; n8++)
                    MMA16816(acc[mt][n8], afr[mt],
                             bfr[n8>>1][n8&1], bfr[n8>>1][2+(n8&1)]);
        }
        if (s + 1 < S) {
            const int nb = buf ^ 1;
            char* base = smem + (nb ? 2*STG : 0);
            *(uint4*)(base + sts_off)                 = ra0;
            *(uint4*)(base + sts_off + 64*SSTR)       = ra1;
            *(uint4*)(base + STG + sts_off)           = rb0;
            *(uint4*)(base + STG + sts_off + 64*SSTR) = rb1;
        }
        __syncthreads();
    }

    // ------------------------------ epilogue ----------------------------------
    const int l4 = lane >> 2;
    const int l2 = (lane & 3) * 2;
    #pragma unroll
    for (int mt = 0; mt < 4; mt++) {
        #pragma unroll
        for (int half = 0; half < 2; half++) {
            const int row = brow + warp_m + mt*16 + l4 + half*8;
            #pragma unroll
            for (int n8 = 0; n8 < 4; n8++) {
                const int col = bcol + warp_n + n8*8 + l2;
                float c0 = acc[mt][n8][half*2 + 0];
                float c1 = acc[mt][n8][half*2 + 1];
                if (task == 0) {
                    float* C = g_sim + (size_t)((b*Tt+tt)*Mm + row)*WM + w*Mm + col;
                    *(float2*)C = make_float2(c0, c1);
                } else if (task == 1) {
                    float* C = g_X + (size_t)row*Dd + col;
                    *(float2*)C = make_float2(c0, c1);
                } else if (task == 2) {
                    __nv_bfloat16* dst = g_inpA + (size_t)row*KT + col;
                    __nv_bfloat16 h0,l0,h1,l1;
                    split2(c0, h0, l0); split2(c1, h1, l1);
                    __nv_bfloat162 hh; hh.x = h0; hh.y = h1;
                    __nv_bfloat162 ll; ll.x = l0; ll.y = l1;
                    *(__nv_bfloat162*)(dst)        = hh;
                    *(__nv_bfloat162*)(dst + 1024) = ll;
                    *(__nv_bfloat162*)(dst + 2048) = hh;
                } else if (task == 3) {
                    float2 bb = *(const float2*)(b1 + col);
                    float* C = g_gi + (size_t)row*(3*Hh) + col;
                    *(float2*)C = make_float2(c0 + bb.x, c1 + bb.y);
                } else {
                    if (col < 3*Hh) {
                        float2 bb = *(const float2*)(b1 + col);
                        float* C = g_gh + (size_t)row*(3*Hh) + col;
                        *(float2*)C = make_float2(c0 + bb.x, c1 + bb.y);
                    } else {
                        const int j = col - 3*Hh;
                        const int bi = row >> 9, m = row & 511;
                        const size_t zr = (size_t)((bi*Tt + t)*Mm + m)*Dd + j;
                        float2 zz = *(const float2*)(zin + zr);
                        float2 bb = *(const float2*)(b2 + j);
                        *(float2*)(outp + zr) = make_float2(c0 + zz.x + bb.x,
                                                            c1 + zz.y + bb.y);
                    }
                }
            }
        }
    }
}

// ============================ conversion kernels ==============================
__global__ void k_convA(const float* __restrict__ src, __nv_bfloat16* __restrict__ dst)
{
    int e = blockIdx.x*256 + threadIdx.x;
    int r = e >> 10, c = e & 1023;
    __nv_bfloat16 h, l; split2(src[e], h, l);
    size_t base = (size_t)r*KT;
    dst[base + c] = h; dst[base + 1024 + c] = l; dst[base + 2048 + c] = h;
}
__global__ void k_convB(const float* __restrict__ src, __nv_bfloat16* __restrict__ dst)
{
    int e = blockIdx.x*256 + threadIdx.x;
    int r = e >> 10, c = e & 1023;
    __nv_bfloat16 h, l; split2(src[e], h, l);
    size_t base = (size_t)r*KT;
    dst[base + c] = h; dst[base + 1024 + c] = h; dst[base + 2048 + c] = l;
}

// ============================ elementwise kernels =============================
__global__ void k_normalize(const float* __restrict__ z)
{
    const int row = blockIdx.x, tid = threadIdx.x;
    __shared__ float red[256];
    const float* src = z + (size_t)row*Dd;
    float s = 0.f;
    for (int d = tid; d < Dd; d += 256) { float v = src[d]; s += v*v; }
    red[tid] = s; __syncthreads();
    for (int st = 128; st > 0; st >>= 1) { if (tid < st) red[tid] += red[tid+st]; __syncthreads(); }
    const float inv = 1.0f / fmaxf(sqrtf(red[0]), 1e-12f);
    const size_t base = (size_t)row*KT;
    for (int d = tid; d < Dd; d += 256) {
        float v = src[d]*inv;
        __nv_bfloat16 h, l; split2(v, h, l);
        g_znA[base + d] = h; g_znA[base + 1024 + d] = l; g_znA[base + 2048 + d] = h;
        g_znB[base + d] = h; g_znB[base + 1024 + d] = h; g_znB[base + 2048 + d] = l;
    }
}

__global__ void k_wksum(const float* __restrict__ Wk)
{
    int d = blockIdx.x*blockDim.x + threadIdx.x;
    if (d < Dd) {
        float s = 0.f;
        for (int r = 0; r < Dd; r++) s += Wk[(size_t)r*Dd + d];
        g_wksum[d] = s;
    }
}

__global__ void k_s0(const float* __restrict__ z, const float* __restrict__ Watt_q)
{
    const int bt = blockIdx.x, tid = threadIdx.x;
    __shared__ float red[256];
    const float* src = z + (size_t)(bt*Mm)*Dd;
    float s = 0.f;
    for (int d = tid; d < Dd; d += 256) s += src[d]*Watt_q[d];
    red[tid] = s; __syncthreads();
    for (int st = 128; st > 0; st >>= 1) { if (tid < st) red[tid] += red[tid+st]; __syncthreads(); }
    if (tid == 0) g_s0[bt] = red[0];
}

__global__ void k_topk(void)
{
    const int row = blockIdx.x, tid = threadIdx.x;
    const int t = (row / Mm) % Tt;
    const int limit = (t >= 2 ? 3 : t + 1) * Mm;
    __shared__ float sv[WM];
    __shared__ float rv[256];
    __shared__ int   rix[256];
    for (int i = tid; i < limit; i += 256) sv[i] = g_sim[(size_t)row*WM + i];
    __syncthreads();
    for (int k = 0; k < KNN; k++) {
        float bv = -INFINITY; int bi = WM;
        for (int i = tid; i < limit; i += 256) {
            float v = sv[i];
            if (v > bv) { bv = v; bi = i; }
        }
        rv[tid] = bv; rix[tid] = bi; __syncthreads();
        for (int s = 128; s > 0; s >>= 1) {
            if (tid < s) {
                float v2 = rv[tid+s]; int i2 = rix[tid+s];
                if (v2 > rv[tid] || (v2 == rv[tid] && i2 < rix[tid])) { rv[tid]=v2; rix[tid]=i2; }
            }
            __syncthreads();
        }
        if (tid == 0) {
            g_vals[row*KNN+k] = rv[0];
            g_idx [row*KNN+k] = rix[0];
            sv[rix[0]] = -INFINITY;
        }
        __syncthreads();
    }
}

__global__ void k_attn_agg(const float* __restrict__ z)
{
    const int row = blockIdx.x, tid = threadIdx.x;   // 128 threads
    const int bt = row / Mm;
    const int t = bt % Tt, b = bt / Tt;
    __shared__ float kf[KNN][Dd];
    __shared__ float red[128];
    __shared__ float kh[KNN], alpha[KNN];
    for (int k = 0; k < KNN; k++) {
        int id = g_idx[row*KNN+k];
        int w = id / Mm, j = id - w*Mm;
        int tt = t - w; if (tt < 0) tt = 0;
        const float* src = z + (size_t)((b*Tt+tt)*Mm + j)*Dd;
        float part = 0.f;
        for (int d = tid; d < Dd; d += 128) { float v = src[d]; kf[k][d] = v; part += v*g_wksum[d]; }
        red[tid] = part; __syncthreads();
        for (int s = 64; s > 0; s >>= 1) { if (tid < s) red[tid] += red[tid+s]; __syncthreads(); }
        if (tid == 0) kh[k] = red[0];
        __syncthreads();
    }
    if (tid == 0) {
        float s = g_s0[bt];
        float l[KNN], mx = -INFINITY;
        for (int k = 0; k < KNN; k++) { l[k] = s*kh[k]; mx = fmaxf(mx, l[k]); }
        float sum = 0.f;
        for (int k = 0; k < KNN; k++) { l[k] = expf(l[k]-mx); sum += l[k]; }
        for (int k = 0; k < KNN; k++)
            alpha[k] = 0.5f*g_vals[row*KNN+k] + 0.5f*(l[k]/sum);
    }
    __syncthreads();
    const size_t base = (size_t)row*KT;
    for (int d = tid; d < Dd; d += 128) {
        float a = 0.f;
        #pragma unroll
        for (int k = 0; k < KNN; k++) a += alpha[k]*kf[k][d];
        __nv_bfloat16 h, l; split2(a, h, l);
        g_aggA[base + d] = h; g_aggA[base + 1024 + d] = l; g_aggA[base + 2048 + d] = h;
    }
}

__global__ void k_layernorm(const float* __restrict__ lnw, const float* __restrict__ lnb)
{
    const int row = blockIdx.x, tid = threadIdx.x;
    __shared__ float xr[Dd];
    __shared__ float red[256];
    const float* p = g_X + (size_t)row*Dd;
    float s = 0.f;
    for (int d = tid; d < Dd; d += 256) { float v = p[d]; xr[d] = v; s += v; }
    red[tid] = s; __syncthreads();
    for (int st = 128; st > 0; st >>= 1) { if (tid < st) red[tid] += red[tid+st]; __syncthreads(); }
    const float mu = red[0] * (1.0f/Dd);
    __syncthreads();
    float v2 = 0.f;
    for (int d = tid; d < Dd; d += 256) { float dv = xr[d]-mu; v2 += dv*dv; }
    red[tid] = v2; __syncthreads();
    for (int st = 128; st > 0; st >>= 1) { if (tid < st) red[tid] += red[tid+st]; __syncthreads(); }
    const float inv = 1.0f / sqrtf(red[0]*(1.0f/Dd) + LN_EPS);
    const size_t base = (size_t)row*KT;
    for (int d = tid; d < Dd; d += 256) {
        float v = (xr[d]-mu)*inv*lnw[d] + lnb[d];
        __nv_bfloat16 h, l; split2(v, h, l);
        g_XlnA[base + d] = h; g_XlnA[base + 1024 + d] = l; g_XlnA[base + 2048 + d] = h;
    }
}

__global__ void k_zero_mem(void)
{
    int e = blockIdx.x*256 + threadIdx.x;
    if (e < Bb*Mm*Hh) g_mem[e] = 0.f;
}

__global__ void k_init_gh(const float* __restrict__ bhh)
{
    int e = blockIdx.x*256 + threadIdx.x;
    g_gh[e] = bhh[e % (3*Hh)];
}

__global__ void k_gru(int t)
{
    const int e = blockIdx.x*256 + threadIdx.x;       // 0 .. B*M*H-1
    const int i = e >> 10;
    const int hc = e & (Hh-1);
    const int b = i >> 9;
    const size_t gir = (size_t)(i + b*(Tt-1)*Mm + t*Mm);
    const float* gi = g_gi + gir*(3*Hh);
    const float* gh = g_gh + (size_t)i*(3*Hh);
    float r  = 1.f/(1.f + expf(-(gi[hc]        + gh[hc])));
    float zg = 1.f/(1.f + expf(-(gi[Hh+hc]     + gh[Hh+hc])));
    float n  = tanhf(gi[2*Hh+hc] + r*gh[2*Hh+hc]);
    size_t mo = (size_t)i*Hh + hc;
    float old = g_mem[mo];
    float nm = (1.f - zg)*n + zg*old;
    g_mem[mo] = nm;
    __nv_bfloat16 h, l; split2(nm, h, l);
    const size_t base = (size_t)i*KT;
    g_memA[base + hc] = h; g_memA[base + 1024 + hc] = l; g_memA[base + 2048 + hc] = h;
}

__global__ void k_copy_mem(float* __restrict__ out_mem)
{
    int e = blockIdx.x*256 + threadIdx.x;
    if (e < Bb*Mm*Hh) out_mem[e] = g_mem[e];
}

// ================================ launch ======================================
extern "C" void kernel_launch(void* const* d_in, const int* in_sizes, int n_in,
                              void* d_out, int out_size)
{
    const float* z      = (const float*)d_in[0];
    const float* Wq     = (const float*)d_in[1];
    const float* Wv     = (const float*)d_in[2];
    const float* Wout   = (const float*)d_in[3];
    const float* ln_w   = (const float*)d_in[4];
    const float* ln_b   = (const float*)d_in[5];
    const float* Watt_q = (const float*)d_in[6];
    const float* Watt_k = (const float*)d_in[7];
    const float* W_ih   = (const float*)d_in[8];
    const float* W_hh   = (const float*)d_in[9];
    const float* b_ih   = (const float*)d_in[10];
    const float* b_hh   = (const float*)d_in[11];
    const float* W_mf   = (const float*)d_in[12];
    const float* b_mf   = (const float*)d_in[13];
    float* out     = (float*)d_out;
    float* out_h   = out;                            // (B,T,M,D)
    float* out_mem = out + (size_t)NROWS*Dd;         // (B,M,H)

    __nv_bfloat16 *pzA, *pWqB, *pWvB, *pWoutB, *pWihB, *pWhhB, *pWmfB;
    cudaGetSymbolAddress((void**)&pzA,    g_zA);
    cudaGetSymbolAddress((void**)&pWqB,   g_WqB);
    cudaGetSymbolAddress((void**)&pWvB,   g_WvB);
    cudaGetSymbolAddress((void**)&pWoutB, g_WoutB);
    cudaGetSymbolAddress((void**)&pWihB,  g_WihB);
    cudaGetSymbolAddress((void**)&pWhhB,  g_WhhB);
    cudaGetSymbolAddress((void**)&pWmfB,  g_WmfB);

    // ---- conversions + parallel precompute ----
    k_normalize<<<NROWS, 256>>>(z);
    k_convA<<<NROWS*Dd/256, 256>>>(z, pzA);
    k_convB<<<Dd*Dd/256, 256>>>(Wq,   pWqB);
    k_convB<<<Dd*Dd/256, 256>>>(Wv,   pWvB);
    k_convB<<<Dd*Dd/256, 256>>>(Wout, pWoutB);
    k_convB<<<3*Hh*Dd/256, 256>>>(W_ih, pWihB);
    k_convB<<<3*Hh*Dd/256, 256>>>(W_hh, pWhhB);
    k_convB<<<Dd*Dd/256, 256>>>(W_mf, pWmfB);
    k_wksum<<<Dd/256, 256>>>(Watt_k);
    k_s0<<<Bb*Tt, 256>>>(z, Watt_q);

    // sims (42 Gram blocks)
    gemm_mma<<<dim3(Mm/BN, Mm/BM, Bb*21), 256>>>(0, 0, nullptr, nullptr, nullptr, nullptr);
    k_topk<<<NROWS, 256>>>();
    k_attn_agg<<<NROWS, 128>>>(z);

    // X = z@Wq^T + agg@Wv^T  -> g_X
    gemm_mma<<<dim3(Dd/BN, NROWS/BM), 256>>>(1, 0, nullptr, nullptr, nullptr, nullptr);
    k_layernorm<<<NROWS, 256>>>(ln_w, ln_b);
    // inp = Xln@Wout^T (split out) ; gi = inp@W_ih^T + b_ih
    gemm_mma<<<dim3(Dd/BN, NROWS/BM), 256>>>(2, 0, nullptr, nullptr, nullptr, nullptr);
    gemm_mma<<<dim3(3*Hh/BN, NROWS/BM), 256>>>(3, 0, b_ih, nullptr, nullptr, nullptr);

    // ---- sequential GRU ----
    k_zero_mem<<<(Bb*Mm*Hh)/256, 256>>>();
    k_init_gh<<<(Bb*Mm*3*Hh)/256, 256>>>(b_hh);
    for (int t = 0; t < Tt; t++) {
        k_gru<<<(Bb*Mm*Hh)/256, 256>>>(t);
        gemm_mma<<<dim3(4*Hh/BN, (Bb*Mm)/BM), 256>>>(4, t, b_hh, b_mf, z, out_h);
    }
    k_copy_mem<<<(Bb*Mm*Hh)/256, 256>>>(out_mem);
}